// round 1
// baseline (speedup 1.0000x reference)
#include <cuda_runtime.h>
#include <math.h>

// Problem constants
#define BATCH 4
#define CH    128
#define N_    4096
#define EPSV  2.220446049250313e-16f
#define SCALE2 144.26950408889634f   // 100 * log2(e):  exp(100*x) == exp2(SCALE2*x)

// ---------------------------------------------------------------------------
// Device scratch (allocation-free rule: static __device__ arrays)
// ---------------------------------------------------------------------------
__device__ float g_xbar[2 * BATCH * CH];          // [which][b][c] column means (0: rs, 1: m)
__device__ float g_theta[BATCH * CH * N_];        // normalized keys   [b][c][m]
__device__ float g_phi[BATCH * CH * N_];          // normalized queries[b][c][n]
__device__ float g_rsT[BATCH * N_ * CH];          // rs transposed     [b][m][c]

// ---------------------------------------------------------------------------
// K0: per-(src,b,c) spatial means.  1024 blocks x 256 threads.
// ---------------------------------------------------------------------------
__global__ void k_means(const float* __restrict__ m_in, const float* __restrict__ rs) {
    int row   = blockIdx.x;            // 0..1023
    int which = row >> 9;              // 0 -> rs (theta), 1 -> m (phi)
    int bc    = row & 511;             // b*128 + c
    const float* src = which ? m_in : rs;
    const float* p = src + (size_t)bc * N_;

    float s = 0.f;
    for (int i = threadIdx.x; i < N_; i += 256) s += p[i];

    __shared__ float sh[256];
    sh[threadIdx.x] = s;
    __syncthreads();
    for (int off = 128; off > 0; off >>= 1) {
        if (threadIdx.x < off) sh[threadIdx.x] += sh[threadIdx.x + off];
        __syncthreads();
    }
    if (threadIdx.x == 0) g_xbar[which * 512 + bc] = sh[0] * (1.0f / N_);
}

// ---------------------------------------------------------------------------
// K1: projection + mean-center + channel-L2-normalize.
//   p_centered = W @ (x - xbar)          (bias cancels under mean-centering)
//   out[:,n]   = p[:,n] / (||p[:,n]||_2 + EPS)
// grid (N/16, BATCH, 2) ; block 128 (thread = output channel o)
// ---------------------------------------------------------------------------
__global__ void k_proj(const float* __restrict__ m_in, const float* __restrict__ rs,
                       const float* __restrict__ theta_w, const float* __restrict__ phi_w) {
    int tile  = blockIdx.x;
    int b     = blockIdx.y;
    int which = blockIdx.z;            // 0: theta from rs, 1: phi from m
    const float* X = which ? m_in : rs;
    const float* W = which ? phi_w : theta_w;
    float* OUT     = which ? g_phi : g_theta;
    const float* xbar = &g_xbar[which * 512 + b * CH];

    int o  = threadIdx.x;              // 0..127
    int n0 = tile * 16;

    __shared__ float Ws[128 * 33];     // W chunk [o][cc], padded
    __shared__ float xs[32 * 16];      // centered x chunk [cc][j]
    __shared__ float sq[128 * 17];     // squares for norm reduction

    float acc[16];
#pragma unroll
    for (int j = 0; j < 16; j++) acc[j] = 0.f;

    for (int c0 = 0; c0 < CH; c0 += 32) {
        // load W chunk (coalesced)
        for (int i = threadIdx.x; i < 128 * 32; i += 128) {
            int oo = i >> 5, cc = i & 31;
            Ws[oo * 33 + cc] = W[oo * CH + c0 + cc];
        }
        // load centered x chunk
        for (int i = threadIdx.x; i < 32 * 16; i += 128) {
            int cc = i >> 4;
            int j  = i & 15;
            int c  = c0 + cc;
            xs[i] = X[((size_t)(b * CH + c)) * N_ + n0 + j] - xbar[c];
        }
        __syncthreads();
#pragma unroll 8
        for (int cc = 0; cc < 32; cc++) {
            float w = Ws[o * 33 + cc];
#pragma unroll
            for (int j = 0; j < 16; j++) acc[j] += w * xs[cc * 16 + j];
        }
        __syncthreads();
    }

    // column norms: sum over o of acc^2, per j
#pragma unroll
    for (int j = 0; j < 16; j++) sq[o * 17 + j] = acc[j] * acc[j];
    for (int off = 64; off > 0; off >>= 1) {
        __syncthreads();
        if (o < off) {
#pragma unroll
            for (int j = 0; j < 16; j++) sq[o * 17 + j] += sq[(o + off) * 17 + j];
        }
    }
    __syncthreads();

#pragma unroll
    for (int j = 0; j < 16; j++) {
        float norm = sqrtf(sq[j]) + EPSV;
        OUT[((size_t)(b * CH + o)) * N_ + n0 + j] = acc[j] / norm;
    }
}

// ---------------------------------------------------------------------------
// K1b: transpose rs -> g_rsT[b][n][c]
// grid (N/32, CH/32, BATCH) block (32,8)
// ---------------------------------------------------------------------------
__global__ void k_transpose(const float* __restrict__ rs) {
    __shared__ float t[32][33];
    int n0 = blockIdx.x << 5;
    int c0 = blockIdx.y << 5;
    int b  = blockIdx.z;
    int tx = threadIdx.x, tyy = threadIdx.y;
    for (int r = tyy; r < 32; r += 8)
        t[r][tx] = rs[((size_t)(b * CH + c0 + r)) * N_ + n0 + tx];
    __syncthreads();
    for (int nn = tyy; nn < 32; nn += 8)
        g_rsT[((size_t)(b * N_ + n0 + nn)) * CH + c0 + tx] = t[tx][nn];
}

// ---------------------------------------------------------------------------
// K2: fused flash attention.
//   S[n,m] = sum_c phi[c,n] * theta[c,m]    (raw f; confidence = rowmax)
//   P      = exp2((S - m_row)*SCALE2)       (online softmax)
//   O[n,c] = sum_m P[n,m] * rs[c,m]
//   y = O/l * rowmax ;  loc = 1/l
// BM=128 rows/CTA, BN=64 keys/tile, 512 threads. grid (N/128, BATCH)
// Thread map: tx = tid&15 (4 cols of S, 8 cols of O), ty = tid>>4 (4 rows)
// ---------------------------------------------------------------------------
__global__ void __launch_bounds__(512, 1)
k_attn(float* __restrict__ out) {
    extern __shared__ float sm[];
    float* Qs  = sm;                        // [c][r]  128*128
    float* Ks  = Qs + 128 * 128;            // [c][mm] 128*64
    float* VsT = Ks + 128 * 64;             // [mm][c] 64*132 (padded)
    float* Ps  = VsT + 64 * 132;            // [r][mm] 128*68 (padded)

    int b   = blockIdx.y;
    int n0  = blockIdx.x << 7;
    int tid = threadIdx.x;
    int tx  = tid & 15;
    int ty  = tid >> 4;                     // 0..31

    // load Q tile (coalesced, conflict-free)
    for (int i = tid; i < 128 * 128; i += 512) {
        int c = i >> 7, r = i & 127;
        Qs[i] = g_phi[((size_t)(b * CH + c)) * N_ + n0 + r];
    }

    float O[4][8];
    float mi[4], li[4];
#pragma unroll
    for (int i = 0; i < 4; i++) {
        mi[i] = -INFINITY;
        li[i] = 0.f;
#pragma unroll
        for (int j = 0; j < 8; j++) O[i][j] = 0.f;
    }

    for (int m0 = 0; m0 < N_; m0 += 64) {
        __syncthreads();   // previous O-GEMM done before overwriting Ks/VsT

        for (int i = tid; i < 128 * 64; i += 512) {
            int c = i >> 6, mm = i & 63;
            Ks[i] = g_theta[((size_t)(b * CH + c)) * N_ + m0 + mm];
        }
        for (int i = tid; i < 64 * 128; i += 512) {
            int mm = i >> 7, c = i & 127;
            VsT[mm * 132 + c] = g_rsT[((size_t)(b * N_ + m0 + mm)) * CH + c];
        }
        __syncthreads();

        // ---- S = Q^T K (4x4 register tile) ----
        float S[4][4];
#pragma unroll
        for (int i = 0; i < 4; i++)
#pragma unroll
            for (int j = 0; j < 4; j++) S[i][j] = 0.f;

#pragma unroll 8
        for (int c = 0; c < 128; c++) {
            float4 q = *reinterpret_cast<const float4*>(Qs + c * 128 + (ty << 2));
            float4 k = *reinterpret_cast<const float4*>(Ks + (c << 6) + (tx << 2));
            float qa[4] = {q.x, q.y, q.z, q.w};
            float ka[4] = {k.x, k.y, k.z, k.w};
#pragma unroll
            for (int i = 0; i < 4; i++)
#pragma unroll
                for (int j = 0; j < 4; j++) S[i][j] += qa[i] * ka[j];
        }

        // ---- online softmax ----
#pragma unroll
        for (int i = 0; i < 4; i++) {
            float v = fmaxf(fmaxf(S[i][0], S[i][1]), fmaxf(S[i][2], S[i][3]));
#pragma unroll
            for (int off = 8; off > 0; off >>= 1)
                v = fmaxf(v, __shfl_xor_sync(0xffffffffu, v, off));
            float mnew  = fmaxf(mi[i], v);
            float alpha = exp2f((mi[i] - mnew) * SCALE2);
            mi[i] = mnew;

            float p0 = exp2f((S[i][0] - mnew) * SCALE2);
            float p1 = exp2f((S[i][1] - mnew) * SCALE2);
            float p2 = exp2f((S[i][2] - mnew) * SCALE2);
            float p3 = exp2f((S[i][3] - mnew) * SCALE2);
            *reinterpret_cast<float4*>(Ps + ((ty << 2) + i) * 68 + (tx << 2)) =
                make_float4(p0, p1, p2, p3);
            li[i] = li[i] * alpha + (p0 + p1 + p2 + p3);
#pragma unroll
            for (int j = 0; j < 8; j++) O[i][j] *= alpha;
        }
        __syncthreads();   // Ps visible

        // ---- O += P @ V^T (4x8 register tile) ----
#pragma unroll 4
        for (int mm = 0; mm < 64; mm++) {
            float pv[4];
#pragma unroll
            for (int i = 0; i < 4; i++) pv[i] = Ps[((ty << 2) + i) * 68 + mm];
            float4 vlo = *reinterpret_cast<const float4*>(VsT + mm * 132 + (tx << 2));
            float4 vhi = *reinterpret_cast<const float4*>(VsT + mm * 132 + 64 + (tx << 2));
            float va[8] = {vlo.x, vlo.y, vlo.z, vlo.w, vhi.x, vhi.y, vhi.z, vhi.w};
#pragma unroll
            for (int i = 0; i < 4; i++)
#pragma unroll
                for (int j = 0; j < 8; j++) O[i][j] += pv[i] * va[j];
        }
    }

    // ---- epilogue: reduce l across the 16 tx lanes, write y and location ----
#pragma unroll
    for (int i = 0; i < 4; i++) {
        float v = li[i];
#pragma unroll
        for (int off = 8; off > 0; off >>= 1)
            v += __shfl_xor_sync(0xffffffffu, v, off);
        li[i] = v;
    }

    float* yout = out;
    float* loc  = out + (size_t)BATCH * CH * N_;
#pragma unroll
    for (int i = 0; i < 4; i++) {
        int   r   = n0 + (ty << 2) + i;
        float inv = 1.0f / li[i];
        float sc  = mi[i] * inv;      // confidence * softmax-normalization
#pragma unroll
        for (int j = 0; j < 4; j++) {
            yout[((size_t)(b * CH + (tx << 2) + j)) * N_ + r]      = O[i][j] * sc;
            yout[((size_t)(b * CH + 64 + (tx << 2) + j)) * N_ + r] = O[i][4 + j] * sc;
        }
        if (tx == 0) loc[(size_t)b * N_ + r] = inv;
    }
}

// ---------------------------------------------------------------------------
extern "C" void kernel_launch(void* const* d_in, const int* in_sizes, int n_in,
                              void* d_out, int out_size) {
    const float* m_in = (const float*)d_in[0];
    const float* rs   = (const float*)d_in[1];
    const float* thw  = (const float*)d_in[2];
    const float* phw  = (const float*)d_in[4];
    float* out = (float*)d_out;

    k_means<<<1024, 256>>>(m_in, rs);
    k_proj<<<dim3(N_ / 16, BATCH, 2), 128>>>(m_in, rs, thw, phw);
    k_transpose<<<dim3(N_ / 32, CH / 32, BATCH), dim3(32, 8)>>>(rs);

    size_t smem = (size_t)(128 * 128 + 128 * 64 + 64 * 132 + 128 * 68) * sizeof(float);
    cudaFuncSetAttribute(k_attn, cudaFuncAttributeMaxDynamicSharedMemorySize, (int)smem);
    k_attn<<<dim3(N_ / 128, BATCH), 512, smem>>>(out);
}

// round 2
// speedup vs baseline: 1.2831x; 1.2831x over previous
#include <cuda_runtime.h>
#include <math.h>

#define BATCH 4
#define CH    128
#define N_    4096
#define EPSV  2.220446049250313e-16f
#define SCALE2 144.26950408889634f   // 100 * log2(e)

// ---------------------------------------------------------------------------
// Device scratch
// ---------------------------------------------------------------------------
__device__ float g_xbar[2 * BATCH * CH];
__device__ float g_theta[BATCH * CH * N_];        // keys    [b][c][m]
__device__ float g_phi[BATCH * CH * N_];          // queries [b][c][n]
__device__ float g_rsT[BATCH * N_ * CH];          // values  [b][m][c]

// ---------------------------------------------------------------------------
// K0: spatial means
// ---------------------------------------------------------------------------
__global__ void k_means(const float* __restrict__ m_in, const float* __restrict__ rs) {
    int row   = blockIdx.x;
    int which = row >> 9;
    int bc    = row & 511;
    const float* src = which ? m_in : rs;
    const float* p = src + (size_t)bc * N_;

    float s = 0.f;
    for (int i = threadIdx.x; i < N_; i += 256) s += p[i];

    __shared__ float sh[256];
    sh[threadIdx.x] = s;
    __syncthreads();
    for (int off = 128; off > 0; off >>= 1) {
        if (threadIdx.x < off) sh[threadIdx.x] += sh[threadIdx.x + off];
        __syncthreads();
    }
    if (threadIdx.x == 0) g_xbar[which * 512 + bc] = sh[0] * (1.0f / N_);
}

// ---------------------------------------------------------------------------
// K1: projection + mean-center + L2-normalize (bias cancels under centering)
// ---------------------------------------------------------------------------
__global__ void k_proj(const float* __restrict__ m_in, const float* __restrict__ rs,
                       const float* __restrict__ theta_w, const float* __restrict__ phi_w) {
    int tile  = blockIdx.x;
    int b     = blockIdx.y;
    int which = blockIdx.z;
    const float* X = which ? m_in : rs;
    const float* W = which ? phi_w : theta_w;
    float* OUT     = which ? g_phi : g_theta;
    const float* xbar = &g_xbar[which * 512 + b * CH];

    int o  = threadIdx.x;
    int n0 = tile * 16;

    __shared__ float Ws[128 * 33];
    __shared__ float xs[32 * 16];
    __shared__ float sq[128 * 17];

    float acc[16];
#pragma unroll
    for (int j = 0; j < 16; j++) acc[j] = 0.f;

    for (int c0 = 0; c0 < CH; c0 += 32) {
        for (int i = threadIdx.x; i < 128 * 32; i += 128) {
            int oo = i >> 5, cc = i & 31;
            Ws[oo * 33 + cc] = W[oo * CH + c0 + cc];
        }
        for (int i = threadIdx.x; i < 32 * 16; i += 128) {
            int cc = i >> 4;
            int j  = i & 15;
            int c  = c0 + cc;
            xs[i] = X[((size_t)(b * CH + c)) * N_ + n0 + j] - xbar[c];
        }
        __syncthreads();
#pragma unroll 8
        for (int cc = 0; cc < 32; cc++) {
            float w = Ws[o * 33 + cc];
#pragma unroll
            for (int j = 0; j < 16; j++) acc[j] += w * xs[cc * 16 + j];
        }
        __syncthreads();
    }

#pragma unroll
    for (int j = 0; j < 16; j++) sq[o * 17 + j] = acc[j] * acc[j];
    for (int off = 64; off > 0; off >>= 1) {
        __syncthreads();
        if (o < off) {
#pragma unroll
            for (int j = 0; j < 16; j++) sq[o * 17 + j] += sq[(o + off) * 17 + j];
        }
    }
    __syncthreads();

#pragma unroll
    for (int j = 0; j < 16; j++) {
        float norm = sqrtf(sq[j]) + EPSV;
        OUT[((size_t)(b * CH + o)) * N_ + n0 + j] = acc[j] / norm;
    }
}

// ---------------------------------------------------------------------------
// K1b: transpose rs -> g_rsT[b][n][c]
// ---------------------------------------------------------------------------
__global__ void k_transpose(const float* __restrict__ rs) {
    __shared__ float t[32][33];
    int n0 = blockIdx.x << 5;
    int c0 = blockIdx.y << 5;
    int b  = blockIdx.z;
    int tx = threadIdx.x, tyy = threadIdx.y;
    for (int r = tyy; r < 32; r += 8)
        t[r][tx] = rs[((size_t)(b * CH + c0 + r)) * N_ + n0 + tx];
    __syncthreads();
    for (int nn = tyy; nn < 32; nn += 8)
        g_rsT[((size_t)(b * N_ + n0 + nn)) * CH + c0 + tx] = t[tx][nn];
}

// ---------------------------------------------------------------------------
// K2: fused flash attention, v2.
// BM=128 rows/CTA, BN=128 keys/tile, 512 threads, grid (32, BATCH).
// tx = tid&31 spans 128 cols (4 each); ty = tid>>5 -> warp owns rows ty*8..+7.
// Q and P fragment loads are warp-uniform -> LDS broadcasts.
// P aliases the K buffer (K dead after S-GEMM). P rows are warp-private.
// ---------------------------------------------------------------------------
#define SKV 132   // padded stride for K/P and V tiles

__global__ void __launch_bounds__(512, 1)
k_attn(float* __restrict__ out) {
    extern __shared__ float sm[];
    float* Qs  = sm;                 // [c][r]  128 x 128, stride 128
    float* KP  = Qs + 128 * 128;     // Ks: [c][mm] stride SKV;  then Ps: [r][mm] stride SKV
    float* VsT = KP + 128 * SKV;     // [mm][c] stride SKV

    int b   = blockIdx.y;
    int n0  = blockIdx.x << 7;
    int tid = threadIdx.x;
    int tx  = tid & 31;
    int ty  = tid >> 5;
    int r0  = ty << 3;               // 8 rows per warp
    int cx  = tx << 2;               // 4 cols/channels per lane

    // load Q tile [c][r] (coalesced float4)
    {
        const float4* src = reinterpret_cast<const float4*>(g_phi + ((size_t)(b * CH)) * N_ + n0);
        for (int i = tid; i < 128 * 32; i += 512) {
            int c = i >> 5, rq = (i & 31) << 2;
            float4 v = __ldg(&src[(size_t)c * (N_ / 4) + (rq >> 2)]);
            *reinterpret_cast<float4*>(Qs + c * 128 + rq) = v;
        }
    }

    float O[8][4];
    float mi[8], li[8];
#pragma unroll
    for (int i = 0; i < 8; i++) {
        mi[i] = -INFINITY;
        li[i] = 0.f;
#pragma unroll
        for (int j = 0; j < 4; j++) O[i][j] = 0.f;
    }

    for (int m0 = 0; m0 < N_; m0 += 128) {
        __syncthreads();   // previous PV done before overwriting KP/VsT

        // load K tile [c][mm] and V tile [mm][c]
        {
            const float4* ks = reinterpret_cast<const float4*>(g_theta + ((size_t)(b * CH)) * N_ + m0);
            const float4* vs = reinterpret_cast<const float4*>(g_rsT + ((size_t)(b * N_ + m0)) * CH);
            for (int i = tid; i < 128 * 32; i += 512) {
                int c = i >> 5, mq = (i & 31) << 2;
                float4 v = __ldg(&ks[(size_t)c * (N_ / 4) + (mq >> 2)]);
                *reinterpret_cast<float4*>(KP + c * SKV + mq) = v;
            }
            for (int i = tid; i < 128 * 32; i += 512) {
                int mm = i >> 5, cq = (i & 31) << 2;
                float4 v = __ldg(&vs[(size_t)mm * (CH / 4) + (cq >> 2)]);
                *reinterpret_cast<float4*>(VsT + mm * SKV + cq) = v;
            }
        }
        __syncthreads();

        // ---- S = Q^T K : 8x4 tile, Q loads are warp-uniform broadcasts ----
        float S[8][4];
#pragma unroll
        for (int i = 0; i < 8; i++)
#pragma unroll
            for (int j = 0; j < 4; j++) S[i][j] = 0.f;

#pragma unroll 8
        for (int c = 0; c < 128; c++) {
            float4 q0 = *reinterpret_cast<const float4*>(Qs + c * 128 + r0);      // broadcast
            float4 q1 = *reinterpret_cast<const float4*>(Qs + c * 128 + r0 + 4);  // broadcast
            float4 k  = *reinterpret_cast<const float4*>(KP + c * SKV + cx);
            float qa[8] = {q0.x, q0.y, q0.z, q0.w, q1.x, q1.y, q1.z, q1.w};
            float ka[4] = {k.x, k.y, k.z, k.w};
#pragma unroll
            for (int i = 0; i < 8; i++)
#pragma unroll
                for (int j = 0; j < 4; j++) S[i][j] += qa[i] * ka[j];
        }
        __syncthreads();   // everyone done reading Ks before P overwrites it

        // ---- online softmax; each row spans exactly one warp ----
#pragma unroll
        for (int i = 0; i < 8; i++) {
            float v = fmaxf(fmaxf(S[i][0], S[i][1]), fmaxf(S[i][2], S[i][3]));
#pragma unroll
            for (int off = 16; off > 0; off >>= 1)
                v = fmaxf(v, __shfl_xor_sync(0xffffffffu, v, off));
            float mnew  = fmaxf(mi[i], v);
            float alpha = exp2f((mi[i] - mnew) * SCALE2);
            mi[i] = mnew;

            float p0 = exp2f((S[i][0] - mnew) * SCALE2);
            float p1 = exp2f((S[i][1] - mnew) * SCALE2);
            float p2 = exp2f((S[i][2] - mnew) * SCALE2);
            float p3 = exp2f((S[i][3] - mnew) * SCALE2);
            *reinterpret_cast<float4*>(KP + (r0 + i) * SKV + cx) =
                make_float4(p0, p1, p2, p3);
            li[i] = li[i] * alpha + (p0 + p1 + p2 + p3);
#pragma unroll
            for (int j = 0; j < 4; j++) O[i][j] *= alpha;
        }
        __syncwarp();      // P rows are warp-private

        // ---- O += P @ V^T : P loads warp-uniform broadcasts ----
#pragma unroll 2
        for (int mm0 = 0; mm0 < 128; mm0 += 4) {
            float4 v0 = *reinterpret_cast<const float4*>(VsT + (mm0 + 0) * SKV + cx);
            float4 v1 = *reinterpret_cast<const float4*>(VsT + (mm0 + 1) * SKV + cx);
            float4 v2 = *reinterpret_cast<const float4*>(VsT + (mm0 + 2) * SKV + cx);
            float4 v3 = *reinterpret_cast<const float4*>(VsT + (mm0 + 3) * SKV + cx);
#pragma unroll
            for (int i = 0; i < 8; i++) {
                float4 p = *reinterpret_cast<const float4*>(KP + (r0 + i) * SKV + mm0); // broadcast
                O[i][0] += p.x * v0.x; O[i][1] += p.x * v0.y; O[i][2] += p.x * v0.z; O[i][3] += p.x * v0.w;
                O[i][0] += p.y * v1.x; O[i][1] += p.y * v1.y; O[i][2] += p.y * v1.z; O[i][3] += p.y * v1.w;
                O[i][0] += p.z * v2.x; O[i][1] += p.z * v2.y; O[i][2] += p.z * v2.z; O[i][3] += p.z * v2.w;
                O[i][0] += p.w * v3.x; O[i][1] += p.w * v3.y; O[i][2] += p.w * v3.z; O[i][3] += p.w * v3.w;
            }
        }
    }

    // ---- epilogue ----
#pragma unroll
    for (int i = 0; i < 8; i++) {
        float v = li[i];
#pragma unroll
        for (int off = 16; off > 0; off >>= 1)
            v += __shfl_xor_sync(0xffffffffu, v, off);
        li[i] = v;
    }

    float* yout = out;
    float* loc  = out + (size_t)BATCH * CH * N_;
#pragma unroll
    for (int i = 0; i < 8; i++) {
        int   r   = n0 + r0 + i;
        float inv = 1.0f / li[i];
        float sc  = mi[i] * inv;
#pragma unroll
        for (int j = 0; j < 4; j++)
            yout[((size_t)(b * CH + cx + j)) * N_ + r] = O[i][j] * sc;
        if (tx == 0) loc[(size_t)b * N_ + r] = inv;
    }
}

// ---------------------------------------------------------------------------
extern "C" void kernel_launch(void* const* d_in, const int* in_sizes, int n_in,
                              void* d_out, int out_size) {
    const float* m_in = (const float*)d_in[0];
    const float* rs   = (const float*)d_in[1];
    const float* thw  = (const float*)d_in[2];
    const float* phw  = (const float*)d_in[4];
    float* out = (float*)d_out;

    k_means<<<1024, 256>>>(m_in, rs);
    k_proj<<<dim3(N_ / 16, BATCH, 2), 128>>>(m_in, rs, thw, phw);
    k_transpose<<<dim3(N_ / 32, CH / 32, BATCH), dim3(32, 8)>>>(rs);

    size_t smem = (size_t)(128 * 128 + 128 * SKV + 128 * SKV) * sizeof(float);
    cudaFuncSetAttribute(k_attn, cudaFuncAttributeMaxDynamicSharedMemorySize, (int)smem);
    k_attn<<<dim3(N_ / 128, BATCH), 512, smem>>>(out);
}